// round 8
// baseline (speedup 1.0000x reference)
#include <cuda_runtime.h>
#include <cuda_bf16.h>

#define NB     32
#define NZ     100
#define STATE  20
#define HIDN   128
#define HH     32
#define WW     32
#define STEPS  64
#define THRESH 0.1f

#define PIX    1024
#define IMG_SZ (STATE*PIX)
#define STATE_SZ (NB*IMG_SZ)
// block = 4 rows x 8 cols; 8 bands x 4 col-strips = 32 blocks/image
#define BPI    32
#define TOTBLK (NB*BPI)      // 1024

// ---------------- persistent device scratch (ping-pong) ----------------
__device__ __align__(16) float g_Tb[2*STATE_SZ];
__device__ unsigned char      g_Pb[2*NB*PIX];
__device__ unsigned char      g_NZb[2*TOTBLK];    // "any pre in block" (=> S may be nonzero)
__device__ unsigned char      g_HOTb[2*TOTBLK];   // "block computed T this step"
__device__ __align__(16) float g_wp_pad[60*128*4];   // [cr=c*3+ky][h][4] (kx 0..2)
__device__ __align__(16) float g_wu1Q  [32*128*4];   // [k>>2][h][4]

// ---------------- f32x2 helpers ----------------
__device__ __forceinline__ unsigned long long pack2(float v) {
    unsigned long long r; asm("mov.b64 %0, {%1, %1};" : "=l"(r) : "f"(v)); return r;
}
__device__ __forceinline__ void fma2(unsigned long long& d,
                                     unsigned long long a, unsigned long long b) {
    asm("fma.rn.f32x2 %0, %1, %2, %0;" : "+l"(d) : "l"(a), "l"(b));
}
__device__ __forceinline__ float2 unpack2(unsigned long long v) {
    float lo, hi; asm("mov.b64 {%0, %1}, %2;" : "=f"(lo), "=f"(hi) : "l"(v));
    return make_float2(lo, hi);
}

// ---------------- weight repack ----------------
__global__ void k_pack(const float* __restrict__ wp, const float* __restrict__ wu1)
{
    int i = blockIdx.x*256 + threadIdx.x;
    if (i < 128*180) {
        int h = i / 180, k = i % 180;            // k = c*9 + ky*3 + kx
        g_wp_pad[(k/3)*512 + h*4 + (k%3)] = wp[i];
    }
    if (i < 128*128) {
        int h = i >> 7, k = i & 127;
        g_wu1Q[(k>>2)*512 + h*4 + (k&3)] = wu1[i];
    }
}

// ---------------- zero buffers (replay determinism) ----------------
__global__ void k_zero()
{
    int i = blockIdx.x*256 + threadIdx.x;
    if (i < STATE_SZ)  g_Tb[i] = 0.f;            // T buffer 0
    if (i < NB*PIX)    g_Pb[i] = 0;              // P buffer 0
    if (i < 2*TOTBLK)  { g_NZb[i] = 0; g_HOTb[i] = 0; }
}

// ---------------- init MLP -> seed into buffer 0 ----------------
__global__ void k_init(const float* __restrict__ z,
                       const float* __restrict__ w1, const float* __restrict__ b1,
                       const float* __restrict__ w2, const float* __restrict__ b2)
{
    int n = blockIdx.x;
    int t = threadIdx.x;
    __shared__ float zz[NZ];
    __shared__ float h[50];
    if (t < NZ) zz[t] = z[n*NZ + t];
    __syncthreads();
    if (t < 50) {
        float a = b1[t];
        #pragma unroll 4
        for (int j = 0; j < NZ; j++) a = fmaf(w1[t*NZ + j], zz[j], a);
        h[t] = fmaxf(a, 0.f);
    }
    __syncthreads();
    const int ctr = 16*WW + 16;
    if (t < STATE-1) {
        float a = b2[t];
        #pragma unroll 5
        for (int j = 0; j < 50; j++) a = fmaf(w2[t*50 + j], h[j], a);
        g_Tb[n*IMG_SZ + (1+t)*PIX + ctr] = a;
    }
    if (t == STATE-1) {
        g_Tb[n*IMG_SZ + ctr] = 0.5f;             // ch0 center
        g_Pb[n*PIX + ctr] = 1;                   // pre-mask: only center alive
        g_NZb[18*32 + n] = 1;                    // center block (band 4, strip 2)
        g_HOTb[18*32 + n] = 1;                   // T valid there (rest of buf0 T is 0 = true value)
    }
}

// ---------------- fused step kernel: one CTA per 4x8 block, 512 threads ----------------
// thread t: h = t&127 (hid ch), q = t>>7 (row 0..3 of block, 8 px each)
__global__ void __launch_bounds__(512)
k_step(int step,
       const float* __restrict__ bp,
       const float* __restrict__ bu1,
       const float* __restrict__ wu2, const float* __restrict__ bu2)
{
    __shared__ __align__(16) float patchA[20*6*12];   // S rows y0-1..y0+4, cols x0-1..x0+9
    __shared__ __align__(16) float patchB[20*6*12];   // shifted by 1 col
    __shared__ __align__(16) float sperc[128*36];     // [k][pp] stride 36
    __shared__ __align__(16) float sh2T[32*132];      // [pp][h] stride 132
    __shared__ float tch0[8*12];                      // T ch0 rows y0-2..y0+5
    __shared__ unsigned char aflag[6*12];
    __shared__ unsigned char s_nz[12];
    __shared__ unsigned char s_hot[12];
    __shared__ int sflag;

    const int in  = step & 1;
    const float* __restrict__ Tin = g_Tb + in*STATE_SZ;
    float*       __restrict__ Tout = g_Tb + (in^1)*STATE_SZ;
    const unsigned char* __restrict__ Pin  = g_Pb + in*NB*PIX;
    unsigned char*       __restrict__ Pout = g_Pb + (in^1)*NB*PIX;
    const unsigned char* __restrict__ NZin  = g_NZb + in*TOTBLK;
    unsigned char*       __restrict__ NZout = g_NZb + (in^1)*TOTBLK;
    const unsigned char* __restrict__ HOTin  = g_HOTb + in*TOTBLK;
    unsigned char*       __restrict__ HOTout = g_HOTb + (in^1)*TOTBLK;

    const int b    = blockIdx.x;          // 0..1023
    const int n    = b & 31;
    const int blk  = b >> 5;              // 0..31
    const int band = blk >> 2;
    const int sx   = blk & 3;
    const int y0   = band << 2;
    const int x0   = sx << 3;
    const int t    = threadIdx.x;
    const int lane = t & 31;

    // ---- hot test: dilate NZ over 3x3 block neighborhood; stage NZ + HOT ----
    if (t < 32) {
        int h1 = 0;
        if (lane < 9) {
            int dy = lane/3 - 1, ds = lane%3 - 1;
            int bb = band + dy, ss = sx + ds;
            int nz = 0, ht = 0;
            if ((unsigned)bb < 8u && (unsigned)ss < 4u) {
                nz = NZin[(bb*4 + ss)*32 + n];
                ht = HOTin[(bb*4 + ss)*32 + n];
            }
            s_nz[lane]  = (unsigned char)nz;
            s_hot[lane] = (unsigned char)ht;
            h1 = nz;
        }
        h1 = __any_sync(0xffffffffu, h1);
        if (lane == 0) {
            sflag = h1;
            HOTout[blk*32 + n] = (unsigned char)h1;
            if (!h1) NZout[blk*32 + n] = 0;      // cold block: kill stale flags
        }
    }
    __syncthreads();
    if (!sflag) return;

    // ---- stage T ch0 region 8x12 (rows y0-2.., cols x0-2..), gated by HOTin ----
    if (t < 96) {
        int rr = t / 12, cc = t % 12;
        int yy = y0 - 2 + rr, xx = x0 - 2 + cc;
        float v = 0.f;
        if ((unsigned)yy < (unsigned)HH && (unsigned)xx < (unsigned)WW) {
            int bdy = (yy >> 2) - band + 1;     // 0..2
            int bds = (xx >> 3) - sx + 1;       // 0..2
            if (s_hot[bdy*3 + bds])
                v = Tin[n*IMG_SZ + yy*WW + xx];
        }
        tch0[rr*12 + cc] = v;
    }
    __syncthreads();

    // ---- alive flags for 6x10 halo (reconstruct mask of S_{t-1}) ----
    if (t < 60) {
        int r = t / 10, col = t % 10;
        int yy = y0 - 1 + r, xx = x0 - 1 + col;
        int f = 0;
        if ((unsigned)yy < (unsigned)HH && (unsigned)xx < (unsigned)WW) {
            int bdy = (yy >> 2) - band + 1;
            int bds = (xx >> 3) - sx + 1;
            if (s_nz[bdy*3 + bds] && Pin[n*PIX + yy*WW + xx]) {
                float m = -1.f;
                #pragma unroll
                for (int dr = 0; dr < 3; dr++)
                    #pragma unroll
                    for (int dc = 0; dc < 3; dc++)
                        m = fmaxf(m, tch0[(r + dr)*12 + (col + dc)]);
                f = (m > THRESH) ? 1 : 0;
            }
        }
        aflag[r*12 + col] = (unsigned char)f;
    }
    __syncthreads();

    // ---- build patchA/patchB = masked S_{t-1} over [20][6][12] ----
    for (int i = t; i < 20*6*12; i += 512) {
        int pr = i / 12, col = i - pr*12;     // pr = c*6 + r
        int c = pr / 6, r = pr - c*6;
        float v = 0.f;
        if (col < 10 && aflag[r*12 + col]) {
            int yy = y0 - 1 + r, xx = x0 - 1 + col;
            v = Tin[n*IMG_SZ + c*PIX + yy*WW + xx];
        }
        patchA[i] = v;
        if (col >= 1) patchB[i - 1] = v;
        else          patchB[pr*12 + 11] = 0.f;
    }
    __syncthreads();

    // ---- pre-mask (this step) for own 32 px + NZout ----
    if (t < 32) {
        int pr0 = t >> 3, pc0 = t & 7;
        float m = 0.f;
        #pragma unroll
        for (int r2 = 0; r2 < 3; r2++)
            #pragma unroll
            for (int c2 = 0; c2 < 3; c2++)
                m = fmaxf(m, patchA[(pr0 + r2)*12 + pc0 + c2]);   // ch0 rows
        int pre = (m > THRESH) ? 1 : 0;
        Pout[n*PIX + (y0 + pr0)*WW + x0 + pc0] = (unsigned char)pre;
        unsigned bal = __ballot_sync(0xffffffffu, pre);
        if (lane == 0) NZout[blk*32 + n] = bal ? 1 : 0;
    }

    const int h = t & 127;
    const int q = t >> 7;               // own row q (0..3)

    // ---- perceive: 3x3 conv 20->128, 8 px (1 row) per thread ----
    unsigned long long acc[4];
    {
        unsigned long long b2v = pack2(__ldg(&bp[h]));
        #pragma unroll
        for (int j = 0; j < 4; j++) acc[j] = b2v;
    }
    #pragma unroll 2
    for (int c = 0; c < STATE; c++) {
        #pragma unroll
        for (int ky = 0; ky < 3; ky++) {
            const float4 w4 = __ldg((const float4*)&g_wp_pad[((c*3 + ky)*128 + h)*4]);
            const unsigned long long W0 = pack2(w4.x);
            const unsigned long long W1 = pack2(w4.y);
            const unsigned long long W2 = pack2(w4.z);
            const int base = (c*6 + ky + q)*12;
            const ulonglong2 A0 = *(const ulonglong2*)&patchA[base];
            const ulonglong2 A1 = *(const ulonglong2*)&patchA[base + 4];
            const unsigned long long A2 = *(const unsigned long long*)&patchA[base + 8];
            const ulonglong2 B0 = *(const ulonglong2*)&patchB[base];
            const ulonglong2 B1 = *(const ulonglong2*)&patchB[base + 4];
            fma2(acc[0], W0, A0.x); fma2(acc[1], W0, A0.y);
            fma2(acc[2], W0, A1.x); fma2(acc[3], W0, A1.y);
            fma2(acc[0], W1, B0.x); fma2(acc[1], W1, B0.y);
            fma2(acc[2], W1, B1.x); fma2(acc[3], W1, B1.y);
            fma2(acc[0], W2, A0.y); fma2(acc[1], W2, A1.x);
            fma2(acc[2], W2, A1.y); fma2(acc[3], W2, A2);
        }
    }
    #pragma unroll
    for (int j = 0; j < 4; j++)
        *(unsigned long long*)&sperc[h*36 + q*8 + 2*j] = acc[j];
    __syncthreads();

    // ---- up1: 1x1 128->128 + relu, 8 px per thread ----
    unsigned long long a1[4];
    {
        unsigned long long b2v = pack2(__ldg(&bu1[h]));
        #pragma unroll
        for (int j = 0; j < 4; j++) a1[j] = b2v;
    }
    const int ppb = q*8;
    #pragma unroll 4
    for (int k4 = 0; k4 < 32; k4++) {
        const float4 w4 = __ldg((const float4*)&g_wu1Q[(k4*128 + h)*4]);
        const float wk[4] = {w4.x, w4.y, w4.z, w4.w};
        #pragma unroll
        for (int j = 0; j < 4; j++) {
            const int k = 4*k4 + j;
            const unsigned long long W = pack2(wk[j]);
            const ulonglong2 v0 = *(const ulonglong2*)&sperc[k*36 + ppb];
            const ulonglong2 v1 = *(const ulonglong2*)&sperc[k*36 + ppb + 4];
            fma2(a1[0], W, v0.x); fma2(a1[1], W, v0.y);
            fma2(a1[2], W, v1.x); fma2(a1[3], W, v1.y);
        }
    }
    #pragma unroll
    for (int j = 0; j < 4; j++) {
        float2 v = unpack2(a1[j]);
        sh2T[(ppb + 2*j + 0)*132 + h] = fmaxf(v.x, 0.f);
        sh2T[(ppb + 2*j + 1)*132 + h] = fmaxf(v.y, 0.f);
    }
    __syncthreads();

    // ---- up2: 1x1 128->20, T_out = S + upd (640 outputs over 512 threads) ----
    #pragma unroll
    for (int round = 0; round < 2; round++) {
        int i2 = t + round*512;
        if (i2 < 640) {
            int c = i2 >> 5, pp = i2 & 31;
            unsigned long long A0 = 0ull, A1 = 0ull;
            const ulonglong2* hv = (const ulonglong2*)&sh2T[pp*132];
            const ulonglong2* wv = (const ulonglong2*)&wu2[c*128];
            #pragma unroll 8
            for (int k4 = 0; k4 < 32; k4++) {
                const ulonglong2 h2 = hv[k4];
                const ulonglong2 w2 = __ldg(&wv[k4]);
                fma2(A0, w2.x, h2.x);
                fma2(A1, w2.y, h2.y);
            }
            float2 s0 = unpack2(A0), s1 = unpack2(A1);
            float a = __ldg(&bu2[c]) + ((s0.x + s0.y) + (s1.x + s1.y));
            int pr0 = pp >> 3, pc0 = pp & 7;
            Tout[n*IMG_SZ + c*PIX + (y0 + pr0)*WW + x0 + pc0] =
                patchA[(c*6 + pr0 + 1)*12 + pc0 + 1] + a;
        }
    }
}

// ---------------- extract: reconstruct masked S_63 ch0 from buffer 0 ----------------
__global__ void k_extract(float* __restrict__ out)
{
    int g = blockIdx.x*256 + threadIdx.x;     // 0..32767
    int n = g >> 10, rem = g & 1023;
    int y = rem >> 5, x = rem & 31;
    int blk = (y >> 2)*4 + (x >> 3);

    float v = 0.f;
    if (g_NZb[blk*32 + n] && g_Pb[n*PIX + rem]) {
        const float* __restrict__ Tn = g_Tb + n*IMG_SZ;
        float m = -1.f;
        #pragma unroll
        for (int dy = -1; dy <= 1; dy++) {
            int yy = y + dy;
            if ((unsigned)yy >= (unsigned)HH) continue;
            #pragma unroll
            for (int dx = -1; dx <= 1; dx++) {
                int xx = x + dx;
                if ((unsigned)xx >= (unsigned)WW) continue;
                m = fmaxf(m, Tn[yy*WW + xx]);
            }
        }
        if (m > THRESH) v = Tn[rem];
    }
    out[g] = v;
}

// ---------------- launch ----------------
extern "C" void kernel_launch(void* const* d_in, const int* in_sizes, int n_in,
                              void* d_out, int out_size)
{
    const float* z   = (const float*)d_in[0];
    const float* w1  = (const float*)d_in[1];
    const float* b1  = (const float*)d_in[2];
    const float* w2  = (const float*)d_in[3];
    const float* b2  = (const float*)d_in[4];
    const float* wp  = (const float*)d_in[5];
    const float* bp  = (const float*)d_in[6];
    const float* wu1 = (const float*)d_in[7];
    const float* bu1 = (const float*)d_in[8];
    const float* wu2 = (const float*)d_in[9];
    const float* bu2 = (const float*)d_in[10];
    float* out = (float*)d_out;

    k_pack<<<(128*180 + 255)/256, 256>>>(wp, wu1);
    k_zero<<<(STATE_SZ + 255)/256, 256>>>();
    k_init<<<NB, 128>>>(z, w1, b1, w2, b2);

    for (int s = 0; s < STEPS; s++)
        k_step<<<TOTBLK, 512>>>(s, bp, bu1, wu2, bu2);

    k_extract<<<(NB*PIX)/256, 256>>>(out);
}

// round 10
// speedup vs baseline: 1.3602x; 1.3602x over previous
#include <cuda_runtime.h>
#include <cuda_bf16.h>

#define NB     32
#define NZ     100
#define STATE  20
#define HIDN   128
#define HH     32
#define WW     32
#define STEPS  64
#define THRESH 0.1f

#define PIX    1024
#define IMG_SZ (STATE*PIX)
#define STATE_SZ (NB*IMG_SZ)
#define SPR    4
#define NSTRIP 128
#define TOTSTRIP 4096

// ---------------- persistent device scratch ----------------
__device__ __align__(16) float g_S[STATE_SZ];
__device__ __align__(16) float g_T[STATE_SZ];
__device__ unsigned char      g_P  [NB*PIX];
__device__ unsigned char      g_HOT[TOTSTRIP];   // strip computed this step
__device__ unsigned char      g_NZ [TOTSTRIP];   // strip has alive pixel
// packed weights: w_perc -> [cr=0..59][hid=0..127][4 slots (3 used)]
__device__ __align__(16) float g_wp_pad [60*128*4];
// w_up1 -> [kg=0..31][hid][4]
__device__ __align__(16) float g_wu1_pad[32*128*4];

// ---------------- weight repack ----------------
__global__ void k_pack(const float* __restrict__ wp, const float* __restrict__ wu1)
{
    int i = blockIdx.x*256 + threadIdx.x;
    if (i < 128*180) {
        int h = i / 180, k = i % 180;            // k = c*9 + r*3 + kx
        g_wp_pad[(k/3)*512 + h*4 + (k%3)] = wp[i];
    }
    if (i < 128*128) {
        int h = i / 128, k = i % 128;
        g_wu1_pad[(k>>2)*512 + h*4 + (k&3)] = wu1[i];
    }
}

// ---------------- zero initial state + flags ----------------
__global__ void k_zero()
{
    int i = blockIdx.x*256 + threadIdx.x;
    if (i < STATE_SZ) g_S[i] = 0.f;
    if (i < TOTSTRIP) g_NZ[i] = 0;
}

// ---------------- init MLP: z -> center pixel ----------------
__global__ void k_init(const float* __restrict__ z,
                       const float* __restrict__ w1, const float* __restrict__ b1,
                       const float* __restrict__ w2, const float* __restrict__ b2)
{
    int n = blockIdx.x;
    int t = threadIdx.x;  // 128 threads
    __shared__ float zz[NZ];
    __shared__ float h[50];
    if (t < NZ) zz[t] = z[n*NZ + t];
    __syncthreads();
    if (t < 50) {
        float a = b1[t];
        #pragma unroll 4
        for (int j = 0; j < NZ; j++) a += w1[t*NZ + j] * zz[j];
        h[t] = fmaxf(a, 0.f);
    }
    __syncthreads();
    const int ctr = 16*WW + 16;
    if (t < STATE-1) {
        float a = b2[t];
        #pragma unroll 5
        for (int j = 0; j < 50; j++) a += w2[t*50 + j] * h[j];
        g_S[n*STATE*PIX + (1+t)*PIX + ctr] = a;
    }
    if (t == STATE-1) {
        g_S[n*STATE*PIX + 0*PIX + ctr] = 0.5f;
        g_NZ[n*NSTRIP + 16*SPR + 2] = 1;     // center strip alive
    }
}

// ---------------- step kernel 1 (R1 core + NZ-dilation gate) ----------------
// grid: (4, 32, 32) = (strip, row, image); block: 128 threads (1 thread = 1 HID channel)
__global__ void __launch_bounds__(128)
k_step1(const float* __restrict__ bp,
        const float* __restrict__ bu1,
        const float* __restrict__ wu2, const float* __restrict__ bu2)
{
    // NOTE: all vector-accessed shared arrays are explicitly 16B-aligned and
    // declared BEFORE the scalar flag (R9's crash: sflag first -> patch at +4B).
    __shared__ __align__(16) float patch[STATE][3][12];
    __shared__ __align__(16) float s_perc[HIDN][8];
    __shared__ __align__(16) float s_h2 [HIDN][8];
    __shared__ int sflag;

    const int sx = blockIdx.x;
    const int x0 = sx * 8;
    const int y  = blockIdx.y;
    const int n  = blockIdx.z;
    const int t  = threadIdx.x;
    const int idx = y*SPR + sx;
    const int se  = n*NSTRIP + idx;

    // ---- hot test: dilate NZ by 5 rows x 3 strip-cols (warp 0) ----
    if (t < 32) {
        int h1 = 0;
        if (t < 15) {
            int dy = t/3 - 2, ds = t%3 - 1;
            int yy = y + dy, ss = sx + ds;
            if ((unsigned)yy < (unsigned)HH && (unsigned)ss < (unsigned)SPR)
                h1 = g_NZ[n*NSTRIP + yy*SPR + ss];
        }
        h1 = __any_sync(0xffffffffu, h1);
        if (t == 0) {
            sflag = h1;
            g_HOT[se] = (unsigned char)h1;
        }
    }
    __syncthreads();
    if (!sflag) return;     // cold: nothing else written

    const float* __restrict__ Sn = g_S + n*STATE*PIX;
    float* __restrict__ Tn = g_T + n*STATE*PIX;

    for (int i = t; i < STATE*3*12; i += 128) {
        int c = i / 36, rem = i - c*36, r = rem / 12, col = rem - r*12;
        int yy = y - 1 + r, xx = x0 - 1 + col;
        float v = 0.f;
        if (col < 10 && (unsigned)yy < (unsigned)HH && (unsigned)xx < (unsigned)WW)
            v = Sn[c*PIX + yy*WW + xx];
        patch[c][r][col] = v;
    }
    __syncthreads();

    // pre living mask for the 8 strip pixels
    if (t < 8) {
        float m = 0.f;
        #pragma unroll
        for (int r = 0; r < 3; r++)
            #pragma unroll
            for (int cc = 0; cc < 3; cc++)
                m = fmaxf(m, patch[0][r][t + cc]);
        g_P[n*PIX + y*WW + x0 + t] = (m > THRESH) ? 1 : 0;
    }

    // ---- perceive: 3x3 conv, 20 -> 128, thread t computes channel t for 8 pixels ----
    float acc[8];
    {
        float b = bp[t];
        #pragma unroll
        for (int p = 0; p < 8; p++) acc[p] = b;
    }
    #pragma unroll 2
    for (int c = 0; c < STATE; c++) {
        #pragma unroll
        for (int r = 0; r < 3; r++) {
            const float4 a = *(const float4*)&patch[c][r][0];
            const float4 b = *(const float4*)&patch[c][r][4];
            const float4 d = *(const float4*)&patch[c][r][8];
            float rv[12] = {a.x,a.y,a.z,a.w, b.x,b.y,b.z,b.w, d.x,d.y,d.z,d.w};
            const float4 w4 = *(const float4*)&g_wp_pad[(c*3 + r)*512 + t*4];
            float wk[3] = {w4.x, w4.y, w4.z};
            #pragma unroll
            for (int kx = 0; kx < 3; kx++)
                #pragma unroll
                for (int p = 0; p < 8; p++)
                    acc[p] = fmaf(wk[kx], rv[p + kx], acc[p]);
        }
    }
    #pragma unroll
    for (int p = 0; p < 8; p++) s_perc[t][p] = acc[p];
    __syncthreads();

    // ---- up1: 1x1 conv 128 -> 128 + ReLU ----
    float acc2[8];
    {
        float b = bu1[t];
        #pragma unroll
        for (int p = 0; p < 8; p++) acc2[p] = b;
    }
    #pragma unroll 4
    for (int kg = 0; kg < 32; kg++) {
        const float4 w4 = *(const float4*)&g_wu1_pad[kg*512 + t*4];
        float wk[4] = {w4.x, w4.y, w4.z, w4.w};
        #pragma unroll
        for (int j = 0; j < 4; j++) {
            int k = kg*4 + j;
            const float4 va = *(const float4*)&s_perc[k][0];
            const float4 vb = *(const float4*)&s_perc[k][4];
            acc2[0] = fmaf(wk[j], va.x, acc2[0]);
            acc2[1] = fmaf(wk[j], va.y, acc2[1]);
            acc2[2] = fmaf(wk[j], va.z, acc2[2]);
            acc2[3] = fmaf(wk[j], va.w, acc2[3]);
            acc2[4] = fmaf(wk[j], vb.x, acc2[4]);
            acc2[5] = fmaf(wk[j], vb.y, acc2[5]);
            acc2[6] = fmaf(wk[j], vb.z, acc2[6]);
            acc2[7] = fmaf(wk[j], vb.w, acc2[7]);
        }
    }
    #pragma unroll
    for (int p = 0; p < 8; p++) s_h2[t][p] = fmaxf(acc2[p], 0.f);
    __syncthreads();

    // ---- up2: 1x1 conv 128 -> 20, then T = S + upd ----
    {
        int c = t >> 3, p = t & 7;
        float a = bu2[c];
        #pragma unroll 8
        for (int k4 = 0; k4 < 32; k4++) {
            const float4 w4 = *(const float4*)&wu2[c*128 + k4*4];
            a = fmaf(w4.x, s_h2[k4*4+0][p], a);
            a = fmaf(w4.y, s_h2[k4*4+1][p], a);
            a = fmaf(w4.z, s_h2[k4*4+2][p], a);
            a = fmaf(w4.w, s_h2[k4*4+3][p], a);
        }
        Tn[c*PIX + y*WW + x0 + p] = patch[c][1][p+1] + a;
    }
    if (t < 32) {
        int i = t + 128;
        int c = i >> 3, p = i & 7;
        float a = bu2[c];
        #pragma unroll 8
        for (int k4 = 0; k4 < 32; k4++) {
            const float4 w4 = *(const float4*)&wu2[c*128 + k4*4];
            a = fmaf(w4.x, s_h2[k4*4+0][p], a);
            a = fmaf(w4.y, s_h2[k4*4+1][p], a);
            a = fmaf(w4.z, s_h2[k4*4+2][p], a);
            a = fmaf(w4.w, s_h2[k4*4+3][p], a);
        }
        Tn[c*PIX + y*WW + x0 + p] = patch[c][1][p+1] + a;
    }
}

// ---------------- step kernel 2: warp per strip, early-exit ----------------
__global__ void __launch_bounds__(256)
k_step2()
{
    const int wid  = threadIdx.x >> 5;
    const int lane = threadIdx.x & 31;
    const int e    = blockIdx.x*8 + wid;       // strip id 0..4095
    const int n    = e >> 7;
    const int idx  = e & 127;
    const int y    = idx >> 2;
    const int x0   = (idx & 3) << 3;

    if (!g_HOT[e]) return;     // NZ=1 => HOT=1, so cold strips have S==0 already

    const int q   = lane >> 2;       // pixel 0..7
    const int cgp = lane & 3;        // channel group (5 ch each)
    const int x   = x0 + q;
    const int px  = y*WW + x;
    const float* __restrict__ Tn = g_T + n*IMG_SZ;
    float* __restrict__ Sn = g_S + n*IMG_SZ;

    int alive = 0;
    if (cgp == 0) {
        if (g_P[n*PIX + px]) {
            float m = -1.f;
            #pragma unroll
            for (int dy = -1; dy <= 1; dy++) {
                int yy = y + dy;
                if ((unsigned)yy >= (unsigned)HH) continue;
                #pragma unroll
                for (int dx = -1; dx <= 1; dx++) {
                    int xx = x + dx;
                    if ((unsigned)xx >= (unsigned)WW) continue;
                    m = fmaxf(m, Tn[yy*WW + xx]);
                }
            }
            alive = (m > THRESH) ? 1 : 0;
        }
    }
    alive = __shfl_sync(0xffffffffu, alive, lane & ~3);
    unsigned bal = __ballot_sync(0xffffffffu, alive);

    #pragma unroll
    for (int i = 0; i < 5; i++) {
        int c = cgp*5 + i;
        Sn[c*PIX + px] = alive ? Tn[c*PIX + px] : 0.f;
    }
    if (lane == 0) g_NZ[e] = bal ? 1 : 0;
}

// ---------------- extract output: ch0 of final state ----------------
__global__ void k_extract(float* __restrict__ out)
{
    int g = blockIdx.x*256 + threadIdx.x;     // 0..32767
    int n = g >> 10, rem = g & 1023;
    out[g] = g_S[n*IMG_SZ + rem];
}

// ---------------- launch ----------------
extern "C" void kernel_launch(void* const* d_in, const int* in_sizes, int n_in,
                              void* d_out, int out_size)
{
    const float* z   = (const float*)d_in[0];
    const float* w1  = (const float*)d_in[1];
    const float* b1  = (const float*)d_in[2];
    const float* w2  = (const float*)d_in[3];
    const float* b2  = (const float*)d_in[4];
    const float* wp  = (const float*)d_in[5];
    const float* bp  = (const float*)d_in[6];
    const float* wu1 = (const float*)d_in[7];
    const float* bu1 = (const float*)d_in[8];
    const float* wu2 = (const float*)d_in[9];
    const float* bu2 = (const float*)d_in[10];
    float* out = (float*)d_out;

    k_pack<<<(128*180 + 255)/256, 256>>>(wp, wu1);
    k_zero<<<(STATE_SZ + 255)/256, 256>>>();
    k_init<<<NB, 128>>>(z, w1, b1, w2, b2);

    for (int s = 0; s < STEPS; s++) {
        k_step1<<<dim3(4, 32, 32), 128>>>(bp, bu1, wu2, bu2);
        k_step2<<<TOTSTRIP/8, 256>>>();
    }
    k_extract<<<(NB*PIX)/256, 256>>>(out);
}

// round 11
// speedup vs baseline: 1.6325x; 1.2001x over previous
#include <cuda_runtime.h>
#include <cuda_bf16.h>

#define NB     32
#define NZ     100
#define STATE  20
#define HIDN   128
#define HH     32
#define WW     32
#define STEPS  64
#define THRESH 0.1f

#define PIX    1024
#define IMG_SZ (STATE*PIX)
#define STATE_SZ (NB*IMG_SZ)
#define SPR    4
#define NSTRIP 128
#define TOTSTRIP 4096

// ---------------- persistent device scratch ----------------
__device__ __align__(16) float g_S[STATE_SZ];
__device__ __align__(16) float g_T[STATE_SZ];
__device__ unsigned char      g_P  [NB*PIX];
__device__ unsigned char      g_HOT[TOTSTRIP];   // strip computed this step
__device__ unsigned char      g_AM [TOTSTRIP];   // per-strip alive-pixel bitmask
// packed weights: w_perc -> [cr=0..59][hid=0..127][4 slots (3 used)]
__device__ __align__(16) float g_wp_pad [60*128*4];
// w_up1 -> [kg=0..31][hid][4]
__device__ __align__(16) float g_wu1_pad[32*128*4];

// ---------------- weight repack ----------------
__global__ void k_pack(const float* __restrict__ wp, const float* __restrict__ wu1)
{
    int i = blockIdx.x*256 + threadIdx.x;
    if (i < 128*180) {
        int h = i / 180, k = i % 180;            // k = c*9 + r*3 + kx
        g_wp_pad[(k/3)*512 + h*4 + (k%3)] = wp[i];
    }
    if (i < 128*128) {
        int h = i / 128, k = i % 128;
        g_wu1_pad[(k>>2)*512 + h*4 + (k&3)] = wu1[i];
    }
}

// ---------------- zero initial state + flags ----------------
__global__ void k_zero()
{
    int i = blockIdx.x*256 + threadIdx.x;
    if (i < STATE_SZ) g_S[i] = 0.f;
    if (i < TOTSTRIP) g_AM[i] = 0;
}

// ---------------- init MLP: z -> center pixel ----------------
__global__ void k_init(const float* __restrict__ z,
                       const float* __restrict__ w1, const float* __restrict__ b1,
                       const float* __restrict__ w2, const float* __restrict__ b2)
{
    int n = blockIdx.x;
    int t = threadIdx.x;  // 128 threads
    __shared__ float zz[NZ];
    __shared__ float h[50];
    if (t < NZ) zz[t] = z[n*NZ + t];
    __syncthreads();
    if (t < 50) {
        float a = b1[t];
        #pragma unroll 4
        for (int j = 0; j < NZ; j++) a += w1[t*NZ + j] * zz[j];
        h[t] = fmaxf(a, 0.f);
    }
    __syncthreads();
    const int ctr = 16*WW + 16;
    if (t < STATE-1) {
        float a = b2[t];
        #pragma unroll 5
        for (int j = 0; j < 50; j++) a += w2[t*50 + j] * h[j];
        g_S[n*STATE*PIX + (1+t)*PIX + ctr] = a;
    }
    if (t == STATE-1) {
        g_S[n*STATE*PIX + 0*PIX + ctr] = 0.5f;
        g_AM[n*NSTRIP + 16*SPR + 2] = 0x01;   // strip (y=16,sx=2), pixel 0 = col 16
    }
}

// ---------------- step kernel 1 (R1 core + pixel-exact alive-mask gate) ----------------
// grid: (4, 32, 32) = (strip, row, image); block: 128 threads (1 thread = 1 HID channel)
__global__ void __launch_bounds__(128)
k_step1(const float* __restrict__ bp,
        const float* __restrict__ bu1,
        const float* __restrict__ wu2, const float* __restrict__ bu2)
{
    __shared__ __align__(16) float patch[STATE][3][12];
    __shared__ __align__(16) float s_perc[HIDN][8];
    __shared__ __align__(16) float s_h2 [HIDN][8];
    __shared__ int sflag;

    const int sx = blockIdx.x;
    const int x0 = sx * 8;
    const int y  = blockIdx.y;
    const int n  = blockIdx.z;
    const int t  = threadIdx.x;
    const int idx = y*SPR + sx;
    const int se  = n*NSTRIP + idx;

    // ---- hot test: any alive pixel in rows y-2..y+2, cols x0-2..x0+9 ----
    if (t < 32) {
        int h1 = 0;
        if (t < 15) {
            int dy = t/3 - 2, ds = t%3 - 1;
            int yy = y + dy, ss = sx + ds;
            if ((unsigned)yy < (unsigned)HH && (unsigned)ss < (unsigned)SPR) {
                unsigned m = g_AM[n*NSTRIP + yy*SPR + ss];
                unsigned cm = (ds == 0) ? 0xFFu : (ds < 0 ? 0xC0u : 0x03u);
                h1 = (m & cm) != 0;
            }
        }
        h1 = __any_sync(0xffffffffu, h1);
        if (t == 0) {
            sflag = h1;
            g_HOT[se] = (unsigned char)h1;
        }
    }
    __syncthreads();
    if (!sflag) return;     // cold: nothing else written

    const float* __restrict__ Sn = g_S + n*STATE*PIX;
    float* __restrict__ Tn = g_T + n*STATE*PIX;

    for (int i = t; i < STATE*3*12; i += 128) {
        int c = i / 36, rem = i - c*36, r = rem / 12, col = rem - r*12;
        int yy = y - 1 + r, xx = x0 - 1 + col;
        float v = 0.f;
        if (col < 10 && (unsigned)yy < (unsigned)HH && (unsigned)xx < (unsigned)WW)
            v = Sn[c*PIX + yy*WW + xx];
        patch[c][r][col] = v;
    }
    __syncthreads();

    // pre living mask for the 8 strip pixels
    if (t < 8) {
        float m = 0.f;
        #pragma unroll
        for (int r = 0; r < 3; r++)
            #pragma unroll
            for (int cc = 0; cc < 3; cc++)
                m = fmaxf(m, patch[0][r][t + cc]);
        g_P[n*PIX + y*WW + x0 + t] = (m > THRESH) ? 1 : 0;
    }

    // ---- perceive: 3x3 conv, 20 -> 128, thread t computes channel t for 8 pixels ----
    float acc[8];
    {
        float b = bp[t];
        #pragma unroll
        for (int p = 0; p < 8; p++) acc[p] = b;
    }
    #pragma unroll 2
    for (int c = 0; c < STATE; c++) {
        #pragma unroll
        for (int r = 0; r < 3; r++) {
            const float4 a = *(const float4*)&patch[c][r][0];
            const float4 b = *(const float4*)&patch[c][r][4];
            const float4 d = *(const float4*)&patch[c][r][8];
            float rv[12] = {a.x,a.y,a.z,a.w, b.x,b.y,b.z,b.w, d.x,d.y,d.z,d.w};
            const float4 w4 = *(const float4*)&g_wp_pad[(c*3 + r)*512 + t*4];
            float wk[3] = {w4.x, w4.y, w4.z};
            #pragma unroll
            for (int kx = 0; kx < 3; kx++)
                #pragma unroll
                for (int p = 0; p < 8; p++)
                    acc[p] = fmaf(wk[kx], rv[p + kx], acc[p]);
        }
    }
    #pragma unroll
    for (int p = 0; p < 8; p++) s_perc[t][p] = acc[p];
    __syncthreads();

    // ---- up1: 1x1 conv 128 -> 128 + ReLU ----
    float acc2[8];
    {
        float b = bu1[t];
        #pragma unroll
        for (int p = 0; p < 8; p++) acc2[p] = b;
    }
    #pragma unroll 4
    for (int kg = 0; kg < 32; kg++) {
        const float4 w4 = *(const float4*)&g_wu1_pad[kg*512 + t*4];
        float wk[4] = {w4.x, w4.y, w4.z, w4.w};
        #pragma unroll
        for (int j = 0; j < 4; j++) {
            int k = kg*4 + j;
            const float4 va = *(const float4*)&s_perc[k][0];
            const float4 vb = *(const float4*)&s_perc[k][4];
            acc2[0] = fmaf(wk[j], va.x, acc2[0]);
            acc2[1] = fmaf(wk[j], va.y, acc2[1]);
            acc2[2] = fmaf(wk[j], va.z, acc2[2]);
            acc2[3] = fmaf(wk[j], va.w, acc2[3]);
            acc2[4] = fmaf(wk[j], vb.x, acc2[4]);
            acc2[5] = fmaf(wk[j], vb.y, acc2[5]);
            acc2[6] = fmaf(wk[j], vb.z, acc2[6]);
            acc2[7] = fmaf(wk[j], vb.w, acc2[7]);
        }
    }
    #pragma unroll
    for (int p = 0; p < 8; p++) s_h2[t][p] = fmaxf(acc2[p], 0.f);
    __syncthreads();

    // ---- up2: 1x1 conv 128 -> 20, then T = S + upd ----
    {
        int c = t >> 3, p = t & 7;
        float a = bu2[c];
        #pragma unroll 8
        for (int k4 = 0; k4 < 32; k4++) {
            const float4 w4 = *(const float4*)&wu2[c*128 + k4*4];
            a = fmaf(w4.x, s_h2[k4*4+0][p], a);
            a = fmaf(w4.y, s_h2[k4*4+1][p], a);
            a = fmaf(w4.z, s_h2[k4*4+2][p], a);
            a = fmaf(w4.w, s_h2[k4*4+3][p], a);
        }
        Tn[c*PIX + y*WW + x0 + p] = patch[c][1][p+1] + a;
    }
    if (t < 32) {
        int i = t + 128;
        int c = i >> 3, p = i & 7;
        float a = bu2[c];
        #pragma unroll 8
        for (int k4 = 0; k4 < 32; k4++) {
            const float4 w4 = *(const float4*)&wu2[c*128 + k4*4];
            a = fmaf(w4.x, s_h2[k4*4+0][p], a);
            a = fmaf(w4.y, s_h2[k4*4+1][p], a);
            a = fmaf(w4.z, s_h2[k4*4+2][p], a);
            a = fmaf(w4.w, s_h2[k4*4+3][p], a);
        }
        Tn[c*PIX + y*WW + x0 + p] = patch[c][1][p+1] + a;
    }
}

// ---------------- step kernel 2: warp per strip, early-exit, writes alive mask ----------------
__global__ void __launch_bounds__(256)
k_step2()
{
    const int wid  = threadIdx.x >> 5;
    const int lane = threadIdx.x & 31;
    const int e    = blockIdx.x*8 + wid;       // strip id 0..4095
    const int n    = e >> 7;
    const int idx  = e & 127;
    const int y    = idx >> 2;
    const int x0   = (idx & 3) << 3;

    if (!g_HOT[e]) return;     // alive strips are always hot, so cold S==0 already

    const int q   = lane >> 2;       // pixel 0..7
    const int cgp = lane & 3;        // channel group (5 ch each)
    const int x   = x0 + q;
    const int px  = y*WW + x;
    const float* __restrict__ Tn = g_T + n*IMG_SZ;
    float* __restrict__ Sn = g_S + n*IMG_SZ;

    int alive = 0;
    if (cgp == 0) {
        if (g_P[n*PIX + px]) {
            float m = -1.f;
            #pragma unroll
            for (int dy = -1; dy <= 1; dy++) {
                int yy = y + dy;
                if ((unsigned)yy >= (unsigned)HH) continue;
                #pragma unroll
                for (int dx = -1; dx <= 1; dx++) {
                    int xx = x + dx;
                    if ((unsigned)xx >= (unsigned)WW) continue;
                    m = fmaxf(m, Tn[yy*WW + xx]);
                }
            }
            alive = (m > THRESH) ? 1 : 0;
        }
    }
    alive = __shfl_sync(0xffffffffu, alive, lane & ~3);
    unsigned bal = __ballot_sync(0xffffffffu, alive);

    #pragma unroll
    for (int i = 0; i < 5; i++) {
        int c = cgp*5 + i;
        Sn[c*PIX + px] = alive ? Tn[c*PIX + px] : 0.f;
    }
    if (lane == 0) {
        unsigned m = 0;
        #pragma unroll
        for (int qq = 0; qq < 8; qq++)
            m |= ((bal >> (4*qq)) & 1u) << qq;
        g_AM[e] = (unsigned char)m;
    }
}

// ---------------- extract output: ch0 of final state ----------------
__global__ void k_extract(float* __restrict__ out)
{
    int g = blockIdx.x*256 + threadIdx.x;     // 0..32767
    int n = g >> 10, rem = g & 1023;
    out[g] = g_S[n*IMG_SZ + rem];
}

// ---------------- launch ----------------
extern "C" void kernel_launch(void* const* d_in, const int* in_sizes, int n_in,
                              void* d_out, int out_size)
{
    const float* z   = (const float*)d_in[0];
    const float* w1  = (const float*)d_in[1];
    const float* b1  = (const float*)d_in[2];
    const float* w2  = (const float*)d_in[3];
    const float* b2  = (const float*)d_in[4];
    const float* wp  = (const float*)d_in[5];
    const float* bp  = (const float*)d_in[6];
    const float* wu1 = (const float*)d_in[7];
    const float* bu1 = (const float*)d_in[8];
    const float* wu2 = (const float*)d_in[9];
    const float* bu2 = (const float*)d_in[10];
    float* out = (float*)d_out;

    k_pack<<<(128*180 + 255)/256, 256>>>(wp, wu1);
    k_zero<<<(STATE_SZ + 255)/256, 256>>>();
    k_init<<<NB, 128>>>(z, w1, b1, w2, b2);

    for (int s = 0; s < STEPS; s++) {
        k_step1<<<dim3(4, 32, 32), 128>>>(bp, bu1, wu2, bu2);
        k_step2<<<TOTSTRIP/8, 256>>>();
    }
    k_extract<<<(NB*PIX)/256, 256>>>(out);
}